// round 6
// baseline (speedup 1.0000x reference)
#include <cuda_runtime.h>
#include <math_constants.h>

// x: (64, 4096, 256) fp32; top-8 over axis 1 (S), sorted desc -> (64, 8, 256)
#define B_DIM 64
#define S_DIM 4096
#define C_DIM 256
#define K_TOP 8

#define CHUNKS 8
#define CHUNK_S (S_DIM / CHUNKS)        // 512
#define GRID1 (B_DIM * CHUNKS)          // 512 blocks x 256 threads

// Partials, layout [b][chunk][k][c]: 4 MiB static scratch. Both the pass-1
// stores and the merge loads are one full 128B line per warp access.
__device__ float g_partial[B_DIM * CHUNKS * K_TOP * C_DIM];
// Per-batch completion counters (zero-init at load; each batch's last block
// resets its counter, so every graph replay starts from zero).
__device__ int g_cnt[B_DIM];

// Compare-exchange keeping max at 'a' (descending order).
__device__ __forceinline__ void ce(float& a, float& b) {
    float hi = fmaxf(a, b);
    float lo = fminf(a, b);
    a = hi; b = lo;
}

// Batcher odd-even mergesort, n=8, 19 CE, descending.
__device__ __forceinline__ void sort8_desc(float (&f)[8]) {
    ce(f[0],f[1]); ce(f[2],f[3]); ce(f[4],f[5]); ce(f[6],f[7]);
    ce(f[0],f[2]); ce(f[1],f[3]); ce(f[4],f[6]); ce(f[5],f[7]);
    ce(f[1],f[2]); ce(f[5],f[6]);
    ce(f[0],f[4]); ce(f[1],f[5]); ce(f[2],f[6]); ce(f[3],f[7]);
    ce(f[2],f[4]); ce(f[3],f[5]);
    ce(f[1],f[2]); ce(f[3],f[4]); ce(f[5],f[6]);
}

// Exact sorted top-8 of the union of two descending-sorted 8-lists.
__device__ __forceinline__ void merge8_desc(float (&t)[8], const float (&g)[8]) {
    #pragma unroll
    for (int i = 0; i < 8; ++i) t[i] = fmaxf(t[i], g[7 - i]);
    ce(t[0],t[4]); ce(t[1],t[5]); ce(t[2],t[6]); ce(t[3],t[7]);
    ce(t[0],t[2]); ce(t[1],t[3]); ce(t[4],t[6]); ce(t[5],t[7]);
    ce(t[0],t[1]); ce(t[2],t[3]); ce(t[4],t[5]); ce(t[6],t[7]);
}

// Fused kernel: block = (batch, chunk); thread = one channel.
// Pass-1 streaming scan, then the LAST block of each batch merges that
// batch's 8 chunk partials and writes the final output.
__global__ __launch_bounds__(256, 4) void kmax_fused_kernel(
    const float* __restrict__ x, float* __restrict__ out)
{
    const int batch = blockIdx.x >> 3;          // / CHUNKS
    const int chunk = blockIdx.x & (CHUNKS - 1);
    const int c = threadIdx.x;

    const float* __restrict__ p =
        x + ((size_t)batch * S_DIM + (size_t)chunk * CHUNK_S) * C_DIM + c;

    float t[8];
    #pragma unroll
    for (int i = 0; i < 8; ++i) t[i] = -CUDART_INF_F;

    #pragma unroll 1
    for (int s = 0; s < CHUNK_S; s += 16) {
        float f[8], g[8];
        // 16 batched scalar loads (each = one 128B line per warp).
        #pragma unroll
        for (int u = 0; u < 8; ++u) f[u] = __ldcs(p + (size_t)(s + u) * C_DIM);
        #pragma unroll
        for (int u = 0; u < 8; ++u) g[u] = __ldcs(p + (size_t)(s + 8 + u) * C_DIM);
        sort8_desc(f);
        sort8_desc(g);
        merge8_desc(f, g);      // f = sorted top-8 of the 16
        merge8_desc(t, f);
    }

    // Store partials: [b][chunk][k][c] -> 8 coalesced 128B-line stores/warp.
    {
        float* __restrict__ o =
            g_partial + (((size_t)(batch * CHUNKS + chunk)) * K_TOP) * C_DIM + c;
        #pragma unroll
        for (int k = 0; k < K_TOP; ++k)
            o[(size_t)k * C_DIM] = t[k];
    }

    // Completion protocol (threadFenceReduction pattern).
    __threadfence();
    __shared__ int s_last;
    __syncthreads();
    if (threadIdx.x == 0)
        s_last = (atomicAdd(&g_cnt[batch], 1) == CHUNKS - 1) ? 1 : 0;
    __syncthreads();
    if (!s_last) return;

    // Last block of this batch: reset counter for the next replay, then merge.
    if (threadIdx.x == 0) g_cnt[batch] = 0;
    __threadfence();

    const float* __restrict__ pp =
        g_partial + ((size_t)batch * CHUNKS * K_TOP) * C_DIM + c;

    float m[8];
    #pragma unroll
    for (int k = 0; k < K_TOP; ++k)
        m[k] = pp[(size_t)k * C_DIM];
    #pragma unroll
    for (int j = 1; j < CHUNKS; ++j) {
        float g[8];
        #pragma unroll
        for (int k = 0; k < K_TOP; ++k)
            g[k] = pp[((size_t)j * K_TOP + k) * C_DIM];
        merge8_desc(m, g);
    }

    float* __restrict__ o = out + (size_t)batch * K_TOP * C_DIM + c;
    #pragma unroll
    for (int k = 0; k < K_TOP; ++k)
        o[(size_t)k * C_DIM] = m[k];
}

extern "C" void kernel_launch(void* const* d_in, const int* in_sizes, int n_in,
                              void* d_out, int out_size) {
    const float* x = (const float*)d_in[0];
    float* out = (float*)d_out;
    kmax_fused_kernel<<<GRID1, 256>>>(x, out);
}